// round 13
// baseline (speedup 1.0000x reference)
#include <cuda_runtime.h>
#include <cstdint>

// Problem-shape constants (fixed for this dataset)
#define NMAX  65536
#define C1    128
#define C2    256
#define COUT  256
#define NN_TILE 1024
#define NSPLIT 8               // known-axis splits for three_nn
#define PARTS 512              // max row-blocks (N/128)

// ---------------- scratch (device globals; no allocation allowed) ----------
__device__ float g_w[NMAX * 3];          // interpolation weights
__device__ int   g_i[NMAX * 3];          // 3-NN global indices
__device__ float g_ps[NSPLIT * NMAX * 3]; // partial top-3 scores per split
__device__ int   g_pi[NSPLIT * NMAX * 3]; // partial top-3 indices per split
__device__ float g_H [NMAX * COUT];      // layer-1 pre-BN output
__device__ float g_H2[NMAX * COUT];      // layer-2 pre-BN output
__device__ float g_psum[COUT * PARTS];   // [col][rowblock] partial sums
__device__ float g_psq [COUT * PARTS];
__device__ float g_scale[COUT];
__device__ float g_shift[COUT];

// ---------------- 1a) 3-NN partial pass (4 pts/thread, 8-way known split) ---
// rank by t = u.k - 0.5|k|^2 (max) — identical ordering to squared distance.
__global__ __launch_bounds__(256) void three_nn_part(
    const float* __restrict__ unknown,
    const int*   __restrict__ ub_cnt,
    const float* __restrict__ known,
    const int*   __restrict__ kb_cnt,
    int N, int B)
{
    __shared__ float4 sk[NN_TILE];

    const int tid  = threadIdx.x;
    const int s    = blockIdx.y;                 // tile-residue this block scans
    const int base = blockIdx.x * 1024;          // 256 threads x 4 points

    int   pn[4], pb[4];
    float ux[4], uy[4], uz[4];
#pragma unroll
    for (int p = 0; p < 4; p++) {
        pn[p] = base + p * 256 + tid;
        pb[p] = -1;
        ux[p] = uy[p] = uz[p] = 0.f;
        if (pn[p] < N) {
            ux[p] = unknown[pn[p]*3+0];
            uy[p] = unknown[pn[p]*3+1];
            uz[p] = unknown[pn[p]*3+2];
        }
    }
    {
        int acc = 0;
        for (int b = 0; b < B; b++) {
            int nx = acc + ub_cnt[b];
#pragma unroll
            for (int p = 0; p < 4; p++)
                if (pn[p] < N && pn[p] >= acc && pn[p] < nx) pb[p] = b;
            acc = nx;
        }
    }

    const float NEG = -__int_as_float(0x7f800000);
    float sc0[4], sc1[4], sc2[4];
    int   ia0[4], ia1[4], ia2[4];
#pragma unroll
    for (int p = 0; p < 4; p++) {
        sc0[p] = sc1[p] = sc2[p] = NEG;
        ia0[p] = ia1[p] = ia2[p] = 0;
    }

    int kacc = 0;
    int tilec = 0;                               // global tile counter (uniform)
    for (int b = 0; b < B; b++) {
        int ks = kacc;
        kacc += kb_cnt[b];
        int ke = kacc;
        bool act[4];
#pragma unroll
        for (int p = 0; p < 4; p++) act[p] = (pb[p] == b);

        for (int t = ks; t < ke; t += NN_TILE, tilec++) {
            if ((tilec & (NSPLIT - 1)) != s) continue;      // uniform skip
            int any = __syncthreads_or((int)(act[0] | act[1] | act[2] | act[3]));
            if (!any) continue;

            int cnt = min(NN_TILE, ke - t);
            __syncthreads();
            for (int i = tid; i < cnt; i += 256) {
                float kx = known[(t + i) * 3 + 0];
                float ky = known[(t + i) * 3 + 1];
                float kz = known[(t + i) * 3 + 2];
                float h  = 0.5f * (kx * kx + ky * ky + kz * kz);
                sk[i] = make_float4(kx, ky, kz, h);
            }
            __syncthreads();

#pragma unroll 2
            for (int j = 0; j < cnt; j++) {
                float4 kk = sk[j];
                int gi = t + j;
#pragma unroll
                for (int p = 0; p < 4; p++) {
                    float sc = fmaf(ux[p], kk.x, fmaf(uy[p], kk.y, fmaf(uz[p], kk.z, -kk.w)));
                    sc = act[p] ? sc : NEG;
                    if (sc > sc2[p]) {
                        if (sc > sc1[p]) {
                            sc2[p] = sc1[p]; ia2[p] = ia1[p];
                            if (sc > sc0[p]) { sc1[p] = sc0[p]; ia1[p] = ia0[p]; sc0[p] = sc; ia0[p] = gi; }
                            else             { sc1[p] = sc;     ia1[p] = gi; }
                        } else { sc2[p] = sc; ia2[p] = gi; }
                    }
                }
            }
        }
    }

#pragma unroll
    for (int p = 0; p < 4; p++) {
        if (pn[p] < N) {
            size_t o = ((size_t)s * N + pn[p]) * 3;
            g_ps[o+0] = sc0[p]; g_ps[o+1] = sc1[p]; g_ps[o+2] = sc2[p];
            g_pi[o+0] = ia0[p]; g_pi[o+1] = ia1[p]; g_pi[o+2] = ia2[p];
        }
    }
}

// ---------------- 1b) merge partials -> weights + indices -------------------
__global__ void three_nn_merge(const float* __restrict__ unknown,
                               const float* __restrict__ known,
                               int N)
{
    int n = blockIdx.x * blockDim.x + threadIdx.x;
    if (n >= N) return;

    float cs[NSPLIT * 3];
    int   ci[NSPLIT * 3];
#pragma unroll
    for (int s = 0; s < NSPLIT; s++) {
        size_t o = ((size_t)s * N + n) * 3;
#pragma unroll
        for (int q = 0; q < 3; q++) {
            cs[s*3+q] = g_ps[o+q];
            ci[s*3+q] = g_pi[o+q];
        }
    }

    const float NEG = -__int_as_float(0x7f800000);
    int   wi[3];
#pragma unroll
    for (int pass = 0; pass < 3; pass++) {
        float bs = NEG; int bidx = 0x7fffffff; int bk = 0;
#pragma unroll
        for (int k = 0; k < NSPLIT * 3; k++) {
            bool better = (cs[k] > bs) || (cs[k] == bs && ci[k] < bidx);
            if (better) { bs = cs[k]; bidx = ci[k]; bk = k; }
        }
        wi[pass] = bidx;
        cs[bk] = NEG; ci[bk] = 0x7fffffff;
    }

    float ux = unknown[n*3], uy = unknown[n*3+1], uz = unknown[n*3+2];
    float d[3];
#pragma unroll
    for (int q = 0; q < 3; q++) {
        int ai = wi[q];
        float dx = ux - known[ai*3+0];
        float dy = uy - known[ai*3+1];
        float dz = uz - known[ai*3+2];
        d[q] = dx*dx + dy*dy + dz*dz;
    }
    float r0 = 1.f/(d[0]+1e-8f), r1 = 1.f/(d[1]+1e-8f), r2 = 1.f/(d[2]+1e-8f);
    float sm = 1.f/(r0+r1+r2);
    g_w[n*3+0] = r0*sm; g_w[n*3+1] = r1*sm; g_w[n*3+2] = r2*sm;
    g_i[n*3+0] = wi[0]; g_i[n*3+1] = wi[1]; g_i[n*3+2] = wi[2];
}

// ---------------- 2) fused SGEMM, k-tile 16, packed f32x2 FMA inner loop -----
// (identical to the Round-10 passing version: static SMEM, in-loop A dup)
// C[m,o] = sum_k A[m,k] * W[o,k]; 128x128 tile, 256 thr, 8x8 microtile.
// MODE 0: A built on the fly = [interp(kf, w, i) | uf]   (K = 384)
// MODE 1: A = relu(bn(Asrc)) with g_scale/g_shift          (K = 256)
template <int K, int MODE>
__global__ __launch_bounds__(256, 2) void gemm_fused(
    const float* __restrict__ Asrc,
    const float* __restrict__ kf,
    const float* __restrict__ uf,
    const float* __restrict__ W,
    float* __restrict__ Cdst)
{
    __shared__ float As[2][16][128];
    __shared__ float Bs[2][16][128];
    __shared__ float ssc[256], ssh[256];

    const int tid = threadIdx.x;
    const int tx = tid & 15;          // 16 threads along N
    const int ty = tid >> 4;          // 16 threads along M
    const int ar = tid >> 1;          // row 0..127 loaded by this thread
    const int ks = (tid & 1) * 8;     // k offset (0 or 8) within 16-wide slice
    const int row0 = blockIdx.y * 128;
    const float* Wb = W + (size_t)blockIdx.x * 128 * K;

    if (MODE == 1) { ssc[tid] = g_scale[tid]; ssh[tid] = g_shift[tid]; }

    const int n = row0 + ar;
    float w0 = 0.f, w1 = 0.f, w2 = 0.f;
    int   j0 = 0,   j1 = 0,   j2 = 0;
    if (MODE == 0) {
        w0 = g_w[n*3+0]; w1 = g_w[n*3+1]; w2 = g_w[n*3+2];
        j0 = g_i[n*3+0]; j1 = g_i[n*3+1]; j2 = g_i[n*3+2];
    }
    if (MODE == 1) __syncthreads();   // ssc/ssh visible

    auto loadA4 = [&](int k0) -> float4 {
        float4 v;
        if (MODE == 0) {
            if (k0 < C2) {
                float4 av = *(const float4*)(kf + (size_t)j0 * C2 + k0);
                float4 bv = *(const float4*)(kf + (size_t)j1 * C2 + k0);
                float4 ev = *(const float4*)(kf + (size_t)j2 * C2 + k0);
                v.x = w0*av.x + w1*bv.x + w2*ev.x;
                v.y = w0*av.y + w1*bv.y + w2*ev.y;
                v.z = w0*av.z + w1*bv.z + w2*ev.z;
                v.w = w0*av.w + w1*bv.w + w2*ev.w;
            } else {
                v = *(const float4*)(uf + (size_t)n * C1 + (k0 - C2));
            }
        } else {
            v = *(const float4*)(Asrc + (size_t)n * COUT + k0);
            v.x = fmaxf(fmaf(v.x, ssc[k0+0], ssh[k0+0]), 0.f);
            v.y = fmaxf(fmaf(v.y, ssc[k0+1], ssh[k0+1]), 0.f);
            v.z = fmaxf(fmaf(v.z, ssc[k0+2], ssh[k0+2]), 0.f);
            v.w = fmaxf(fmaf(v.w, ssc[k0+3], ssh[k0+3]), 0.f);
        }
        return v;
    };

    // packed accumulators: acc2[i][jp] = (C[i][2jp], C[i][2jp+1]) within microtile
    unsigned long long acc2[8][4];
#pragma unroll
    for (int i = 0; i < 8; i++)
#pragma unroll
        for (int jp = 0; jp < 4; jp++) acc2[i][jp] = 0ULL;

    // prologue: fill buffer 0 (k-slice [0,16))
    {
        float4 a0 = loadA4(ks);
        float4 a1 = loadA4(ks + 4);
        float4 q0 = *(const float4*)(Wb + (size_t)ar * K + ks);
        float4 q1 = *(const float4*)(Wb + (size_t)ar * K + ks + 4);
        As[0][ks+0][ar] = a0.x; As[0][ks+1][ar] = a0.y;
        As[0][ks+2][ar] = a0.z; As[0][ks+3][ar] = a0.w;
        As[0][ks+4][ar] = a1.x; As[0][ks+5][ar] = a1.y;
        As[0][ks+6][ar] = a1.z; As[0][ks+7][ar] = a1.w;
        Bs[0][ks+0][ar] = q0.x; Bs[0][ks+1][ar] = q0.y;
        Bs[0][ks+2][ar] = q0.z; Bs[0][ks+3][ar] = q0.w;
        Bs[0][ks+4][ar] = q1.x; Bs[0][ks+5][ar] = q1.y;
        Bs[0][ks+6][ar] = q1.z; Bs[0][ks+7][ar] = q1.w;
    }
    __syncthreads();

    const uint32_t bs_base = (uint32_t)__cvta_generic_to_shared(&Bs[0][0][0]);

    const int NK = K / 16;
#pragma unroll 1
    for (int kt = 0; kt < NK; kt++) {
        const int buf = kt & 1;
        float4 na0, na1, nq0, nq1;
        if (kt + 1 < NK) {
            const int kb = (kt + 1) * 16;
            na0 = loadA4(kb + ks);
            na1 = loadA4(kb + ks + 4);
            nq0 = *(const float4*)(Wb + (size_t)ar * K + kb + ks);
            nq1 = *(const float4*)(Wb + (size_t)ar * K + kb + ks + 4);
        }
        const uint32_t bbase = bs_base + ((uint32_t)buf * 2048 + (uint32_t)tx * 4) * 4;
#pragma unroll
        for (int k = 0; k < 16; k++) {
            float4 a0 = *(const float4*)&As[buf][k][ty * 8];
            float4 a1 = *(const float4*)&As[buf][k][ty * 8 + 4];
            unsigned long long b2[4];
            uint32_t baddr = bbase + (uint32_t)k * 512;
            asm volatile("ld.shared.v2.b64 {%0,%1}, [%2];"
                         : "=l"(b2[0]), "=l"(b2[1]) : "r"(baddr));
            asm volatile("ld.shared.v2.b64 {%0,%1}, [%2];"
                         : "=l"(b2[2]), "=l"(b2[3]) : "r"(baddr + 256));
            float ra[8] = {a0.x, a0.y, a0.z, a0.w, a1.x, a1.y, a1.z, a1.w};
#pragma unroll
            for (int i = 0; i < 8; i++) {
                unsigned long long ad;
                asm("mov.b64 %0, {%1, %1};" : "=l"(ad) : "f"(ra[i]));
                asm("fma.rn.f32x2 %0, %1, %2, %0;" : "+l"(acc2[i][0]) : "l"(ad), "l"(b2[0]));
                asm("fma.rn.f32x2 %0, %1, %2, %0;" : "+l"(acc2[i][1]) : "l"(ad), "l"(b2[1]));
                asm("fma.rn.f32x2 %0, %1, %2, %0;" : "+l"(acc2[i][2]) : "l"(ad), "l"(b2[2]));
                asm("fma.rn.f32x2 %0, %1, %2, %0;" : "+l"(acc2[i][3]) : "l"(ad), "l"(b2[3]));
            }
        }
        if (kt + 1 < NK) {
            const int nb = buf ^ 1;
            As[nb][ks+0][ar] = na0.x; As[nb][ks+1][ar] = na0.y;
            As[nb][ks+2][ar] = na0.z; As[nb][ks+3][ar] = na0.w;
            As[nb][ks+4][ar] = na1.x; As[nb][ks+5][ar] = na1.y;
            As[nb][ks+6][ar] = na1.z; As[nb][ks+7][ar] = na1.w;
            Bs[nb][ks+0][ar] = nq0.x; Bs[nb][ks+1][ar] = nq0.y;
            Bs[nb][ks+2][ar] = nq0.z; Bs[nb][ks+3][ar] = nq0.w;
            Bs[nb][ks+4][ar] = nq1.x; Bs[nb][ks+5][ar] = nq1.y;
            Bs[nb][ks+6][ar] = nq1.z; Bs[nb][ks+7][ar] = nq1.w;
        }
        __syncthreads();
    }

    // unpack accumulators (same column mapping as scalar version)
    float acc[8][8];
#pragma unroll
    for (int i = 0; i < 8; i++)
#pragma unroll
        for (int jp = 0; jp < 4; jp++) {
            asm("mov.b64 {%0, %1}, %2;"
                : "=f"(acc[i][2*jp+0]), "=f"(acc[i][2*jp+1]) : "l"(acc2[i][jp]));
        }

    // ---- C store ----
    float* Cb = Cdst + (size_t)(row0 + ty * 8) * COUT + blockIdx.x * 128;
#pragma unroll
    for (int i = 0; i < 8; i++) {
        *(float4*)(Cb + (size_t)i * COUT + tx * 4)      = make_float4(acc[i][0], acc[i][1], acc[i][2], acc[i][3]);
        *(float4*)(Cb + (size_t)i * COUT + 64 + tx * 4) = make_float4(acc[i][4], acc[i][5], acc[i][6], acc[i][7]);
    }

    // ---- BN-stat epilogue (deterministic fixed-order reduce) ----
    float cs[8], cq[8];
#pragma unroll
    for (int j = 0; j < 8; j++) { cs[j] = 0.f; cq[j] = 0.f; }
#pragma unroll
    for (int i = 0; i < 8; i++)
#pragma unroll
        for (int j = 0; j < 8; j++) {
            float v = acc[i][j];
            cs[j] += v;
            cq[j] = fmaf(v, v, cq[j]);
        }
    float (*ps)[128] = reinterpret_cast<float(*)[128]>(&As[0][0][0]);
    float (*pq)[128] = reinterpret_cast<float(*)[128]>(&Bs[0][0][0]);
    __syncthreads();
#pragma unroll
    for (int j = 0; j < 4; j++) {
        ps[ty][tx*4 + j]      = cs[j];
        pq[ty][tx*4 + j]      = cq[j];
        ps[ty][64 + tx*4 + j] = cs[4 + j];
        pq[ty][64 + tx*4 + j] = cq[4 + j];
    }
    __syncthreads();
    if (tid < 128) {
        float sv = 0.f, qv = 0.f;
#pragma unroll
        for (int t16 = 0; t16 < 16; t16++) { sv += ps[t16][tid]; qv += pq[t16][tid]; }
        int c = blockIdx.x * 128 + tid;
        g_psum[(size_t)c * PARTS + blockIdx.y] = sv;
        g_psq [(size_t)c * PARTS + blockIdx.y] = qv;
    }
}

// ---------------- 3) parallel BN finalize (one block per column) ------------
__global__ __launch_bounds__(256) void finalize_par(
    const float* __restrict__ gamma,
    const float* __restrict__ beta,
    int N, int nblk)
{
    __shared__ double sd[256], sq[256];
    const int c = blockIdx.x;
    const int t = threadIdx.x;
    double v = 0.0, q = 0.0;
    for (int b = t; b < nblk; b += 256) {
        v += (double)g_psum[(size_t)c * PARTS + b];
        q += (double)g_psq [(size_t)c * PARTS + b];
    }
    sd[t] = v; sq[t] = q;
    __syncthreads();
    for (int off = 128; off > 0; off >>= 1) {
        if (t < off) { sd[t] += sd[t + off]; sq[t] += sq[t + off]; }
        __syncthreads();
    }
    if (t == 0) {
        double mean = sd[0] / (double)N;
        double var  = sq[0] / (double)N - mean * mean;
        float  sc   = gamma[c] * rsqrtf((float)var + 1e-5f);
        g_scale[c] = sc;
        g_shift[c] = beta[c] - (float)mean * sc;
    }
}

// ---------------- 4) final BN apply + ReLU (vectorized) ----------------------
__global__ void bn_relu_out4(const float4* __restrict__ H, float4* __restrict__ out, int total4)
{
    int t = blockIdx.x * blockDim.x + threadIdx.x;
    if (t < total4) {
        int c = (t & 63) * 4;
        float4 v = H[t];
        v.x = fmaxf(fmaf(v.x, g_scale[c+0], g_shift[c+0]), 0.f);
        v.y = fmaxf(fmaf(v.y, g_scale[c+1], g_shift[c+1]), 0.f);
        v.z = fmaxf(fmaf(v.z, g_scale[c+2], g_shift[c+2]), 0.f);
        v.w = fmaxf(fmaf(v.w, g_scale[c+3], g_shift[c+3]), 0.f);
        out[t] = v;
    }
}

// ---------------- launch -----------------------------------------------------
extern "C" void kernel_launch(void* const* d_in, const int* in_sizes, int n_in,
                              void* d_out, int out_size)
{
    const float* unknown = (const float*)d_in[0];
    const int*   ub_cnt  = (const int*)  d_in[1];
    const float* known   = (const float*)d_in[2];
    const int*   kb_cnt  = (const int*)  d_in[3];
    const float* uf      = (const float*)d_in[4];
    const float* kf      = (const float*)d_in[5];
    const float* W1      = (const float*)d_in[6];
    const float* g1      = (const float*)d_in[7];
    const float* b1      = (const float*)d_in[8];
    const float* W2      = (const float*)d_in[9];
    const float* g2      = (const float*)d_in[10];
    const float* b2      = (const float*)d_in[11];
    float* out = (float*)d_out;

    int N = in_sizes[0] / 3;
    int B = in_sizes[1];
    int nblk = N / 128;
    int total4 = (int)(((long)N * COUT) / 4);

    float* Hp = nullptr; float* H2p = nullptr;
    cudaGetSymbolAddress((void**)&Hp,  g_H);
    cudaGetSymbolAddress((void**)&H2p, g_H2);

    three_nn_part<<<dim3((N + 1023) / 1024, NSPLIT), 256>>>(unknown, ub_cnt, known, kb_cnt, N, B);
    three_nn_merge<<<(N + 255) / 256, 256>>>(unknown, known, N);

    gemm_fused<384, 0><<<dim3(2, nblk), 256>>>(nullptr, kf, uf, W1, Hp);
    finalize_par<<<COUT, 256>>>(g1, b1, N, nblk);

    gemm_fused<256, 1><<<dim3(2, nblk), 256>>>(Hp, nullptr, nullptr, W2, H2p);
    finalize_par<<<COUT, 256>>>(g2, b2, N, nblk);

    bn_relu_out4<<<(total4 + 255) / 256, 256>>>((const float4*)H2p, (float4*)out, total4);
}

// round 15
// speedup vs baseline: 1.1092x; 1.1092x over previous
#include <cuda_runtime.h>
#include <cstdint>

// Problem-shape constants (fixed for this dataset)
#define NMAX  65536
#define C1    128
#define C2    256
#define COUT  256
#define NN_TILE 512
#define NSPLIT 8               // per-batch known-axis splits for three_nn
#define PARTS 512              // max row-blocks (N/128)

// ---------------- scratch (device globals; no allocation allowed) ----------
__device__ float g_w[NMAX * 3];          // interpolation weights
__device__ int   g_i[NMAX * 3];          // 3-NN global indices
__device__ float g_ps[NSPLIT * NMAX * 3]; // partial top-3 scores per split
__device__ int   g_pi[NSPLIT * NMAX * 3]; // partial top-3 indices per split
__device__ float g_H [NMAX * COUT];      // layer-1 pre-BN output
__device__ float g_H2[NMAX * COUT];      // layer-2 pre-BN output
__device__ float g_psum[COUT * PARTS];   // [col][rowblock] partial sums
__device__ float g_psq [COUT * PARTS];
__device__ float g_scale[COUT];
__device__ float g_shift[COUT];

// ---------------- 0) nop kernel (shifts ncu capture onto gemm2) -------------
__global__ void nop_kernel() {}

// ---------------- 1a) 3-NN partial pass (2 pts/thread, 8-way per-batch split)
// rank by t = u.k - 0.5|k|^2 (max) — identical ordering to squared distance.
__global__ __launch_bounds__(256) void three_nn_part(
    const float* __restrict__ unknown,
    const int*   __restrict__ ub_cnt,
    const float* __restrict__ known,
    const int*   __restrict__ kb_cnt,
    int N, int B)
{
    __shared__ float4 sk[NN_TILE];

    const int tid  = threadIdx.x;
    const int s    = blockIdx.y;                 // chunk-residue this block scans
    const int base = blockIdx.x * 512;           // 256 threads x 2 points
    const int n0 = base + tid;
    const int n1 = base + 256 + tid;

    float ux0 = 0.f, uy0 = 0.f, uz0 = 0.f;
    float ux1 = 0.f, uy1 = 0.f, uz1 = 0.f;
    int b0i = -1, b1i = -1;
    if (n0 < N) { ux0 = unknown[n0*3]; uy0 = unknown[n0*3+1]; uz0 = unknown[n0*3+2]; }
    if (n1 < N) { ux1 = unknown[n1*3]; uy1 = unknown[n1*3+1]; uz1 = unknown[n1*3+2]; }
    {
        int acc = 0;
        for (int b = 0; b < B; b++) {
            int nx = acc + ub_cnt[b];
            if (n0 < N && n0 >= acc && n0 < nx) b0i = b;
            if (n1 < N && n1 >= acc && n1 < nx) b1i = b;
            acc = nx;
        }
    }

    const float NEG = -__int_as_float(0x7f800000);
    float s00 = NEG, s01 = NEG, s02 = NEG;
    float s10 = NEG, s11 = NEG, s12 = NEG;
    int   a00 = 0, a01 = 0, a02 = 0;
    int   a10 = 0, a11 = 0, a12 = 0;

    int kacc = 0;
    for (int b = 0; b < B; b++) {
        int ks = kacc;
        kacc += kb_cnt[b];
        int ke = kacc;
        bool act0 = (b0i == b), act1 = (b1i == b);

        int tloc = 0;                            // chunk index WITHIN this batch
        for (int t = ks; t < ke; t += NN_TILE, tloc++) {
            if ((tloc & (NSPLIT - 1)) != s) continue;   // uniform, balanced skip
            int any = __syncthreads_or((int)(act0 || act1));
            if (!any) continue;

            int cnt = min(NN_TILE, ke - t);
            __syncthreads();
            for (int i = tid; i < cnt; i += 256) {
                float kx = known[(t + i) * 3 + 0];
                float ky = known[(t + i) * 3 + 1];
                float kz = known[(t + i) * 3 + 2];
                float h  = 0.5f * (kx * kx + ky * ky + kz * kz);
                sk[i] = make_float4(kx, ky, kz, h);
            }
            __syncthreads();

#pragma unroll 4
            for (int j = 0; j < cnt; j++) {
                float4 kk = sk[j];
                int gi = t + j;
                float t0 = fmaf(ux0, kk.x, fmaf(uy0, kk.y, fmaf(uz0, kk.z, -kk.w)));
                float t1 = fmaf(ux1, kk.x, fmaf(uy1, kk.y, fmaf(uz1, kk.z, -kk.w)));
                t0 = act0 ? t0 : NEG;            // branchless batch mask
                t1 = act1 ? t1 : NEG;
                if (t0 > s02) {
                    if (t0 > s01) {
                        s02 = s01; a02 = a01;
                        if (t0 > s00) { s01 = s00; a01 = a00; s00 = t0; a00 = gi; }
                        else          { s01 = t0;  a01 = gi; }
                    } else { s02 = t0; a02 = gi; }
                }
                if (t1 > s12) {
                    if (t1 > s11) {
                        s12 = s11; a12 = a11;
                        if (t1 > s10) { s11 = s10; a11 = a10; s10 = t1; a10 = gi; }
                        else          { s11 = t1;  a11 = gi; }
                    } else { s12 = t1; a12 = gi; }
                }
            }
        }
    }

    if (n0 < N) {
        size_t o = ((size_t)s * N + n0) * 3;
        g_ps[o+0] = s00; g_ps[o+1] = s01; g_ps[o+2] = s02;
        g_pi[o+0] = a00; g_pi[o+1] = a01; g_pi[o+2] = a02;
    }
    if (n1 < N) {
        size_t o = ((size_t)s * N + n1) * 3;
        g_ps[o+0] = s10; g_ps[o+1] = s11; g_ps[o+2] = s12;
        g_pi[o+0] = a10; g_pi[o+1] = a11; g_pi[o+2] = a12;
    }
}

// ---------------- 1b) merge partials -> weights + indices -------------------
__global__ void three_nn_merge(const float* __restrict__ unknown,
                               const float* __restrict__ known,
                               int N)
{
    int n = blockIdx.x * blockDim.x + threadIdx.x;
    if (n >= N) return;

    float cs[NSPLIT * 3];
    int   ci[NSPLIT * 3];
#pragma unroll
    for (int s = 0; s < NSPLIT; s++) {
        size_t o = ((size_t)s * N + n) * 3;
#pragma unroll
        for (int q = 0; q < 3; q++) {
            cs[s*3+q] = g_ps[o+q];
            ci[s*3+q] = g_pi[o+q];
        }
    }

    const float NEG = -__int_as_float(0x7f800000);
    int   wi[3];
#pragma unroll
    for (int pass = 0; pass < 3; pass++) {
        float bs = NEG; int bidx = 0x7fffffff; int bk = 0;
#pragma unroll
        for (int k = 0; k < NSPLIT * 3; k++) {
            bool better = (cs[k] > bs) || (cs[k] == bs && ci[k] < bidx);
            if (better) { bs = cs[k]; bidx = ci[k]; bk = k; }
        }
        wi[pass] = bidx;
        cs[bk] = NEG; ci[bk] = 0x7fffffff;
    }

    float ux = unknown[n*3], uy = unknown[n*3+1], uz = unknown[n*3+2];
    float d[3];
#pragma unroll
    for (int q = 0; q < 3; q++) {
        int ai = wi[q];
        float dx = ux - known[ai*3+0];
        float dy = uy - known[ai*3+1];
        float dz = uz - known[ai*3+2];
        d[q] = dx*dx + dy*dy + dz*dz;
    }
    float r0 = 1.f/(d[0]+1e-8f), r1 = 1.f/(d[1]+1e-8f), r2 = 1.f/(d[2]+1e-8f);
    float sm = 1.f/(r0+r1+r2);
    g_w[n*3+0] = r0*sm; g_w[n*3+1] = r1*sm; g_w[n*3+2] = r2*sm;
    g_i[n*3+0] = wi[0]; g_i[n*3+1] = wi[1]; g_i[n*3+2] = wi[2];
}

// ---------------- 2) fused SGEMM, k-tile 16, packed f32x2 FMA inner loop -----
// (Round-10 proven version: static SMEM, in-loop A dup via mov.b64)
// C[m,o] = sum_k A[m,k] * W[o,k]; 128x128 tile, 256 thr, 8x8 microtile.
// MODE 0: A built on the fly = [interp(kf, w, i) | uf]   (K = 384)
// MODE 1: A = relu(bn(Asrc)) with g_scale/g_shift          (K = 256)
template <int K, int MODE>
__global__ __launch_bounds__(256, 2) void gemm_fused(
    const float* __restrict__ Asrc,
    const float* __restrict__ kf,
    const float* __restrict__ uf,
    const float* __restrict__ W,
    float* __restrict__ Cdst)
{
    __shared__ float As[2][16][128];
    __shared__ float Bs[2][16][128];
    __shared__ float ssc[256], ssh[256];

    const int tid = threadIdx.x;
    const int tx = tid & 15;          // 16 threads along N
    const int ty = tid >> 4;          // 16 threads along M
    const int ar = tid >> 1;          // row 0..127 loaded by this thread
    const int ks = (tid & 1) * 8;     // k offset (0 or 8) within 16-wide slice
    const int row0 = blockIdx.y * 128;
    const float* Wb = W + (size_t)blockIdx.x * 128 * K;

    if (MODE == 1) { ssc[tid] = g_scale[tid]; ssh[tid] = g_shift[tid]; }

    const int n = row0 + ar;
    float w0 = 0.f, w1 = 0.f, w2 = 0.f;
    int   j0 = 0,   j1 = 0,   j2 = 0;
    if (MODE == 0) {
        w0 = g_w[n*3+0]; w1 = g_w[n*3+1]; w2 = g_w[n*3+2];
        j0 = g_i[n*3+0]; j1 = g_i[n*3+1]; j2 = g_i[n*3+2];
    }
    if (MODE == 1) __syncthreads();   // ssc/ssh visible

    auto loadA4 = [&](int k0) -> float4 {
        float4 v;
        if (MODE == 0) {
            if (k0 < C2) {
                float4 av = *(const float4*)(kf + (size_t)j0 * C2 + k0);
                float4 bv = *(const float4*)(kf + (size_t)j1 * C2 + k0);
                float4 ev = *(const float4*)(kf + (size_t)j2 * C2 + k0);
                v.x = w0*av.x + w1*bv.x + w2*ev.x;
                v.y = w0*av.y + w1*bv.y + w2*ev.y;
                v.z = w0*av.z + w1*bv.z + w2*ev.z;
                v.w = w0*av.w + w1*bv.w + w2*ev.w;
            } else {
                v = *(const float4*)(uf + (size_t)n * C1 + (k0 - C2));
            }
        } else {
            v = *(const float4*)(Asrc + (size_t)n * COUT + k0);
            v.x = fmaxf(fmaf(v.x, ssc[k0+0], ssh[k0+0]), 0.f);
            v.y = fmaxf(fmaf(v.y, ssc[k0+1], ssh[k0+1]), 0.f);
            v.z = fmaxf(fmaf(v.z, ssc[k0+2], ssh[k0+2]), 0.f);
            v.w = fmaxf(fmaf(v.w, ssc[k0+3], ssh[k0+3]), 0.f);
        }
        return v;
    };

    // packed accumulators: acc2[i][jp] = (C[i][2jp], C[i][2jp+1]) within microtile
    unsigned long long acc2[8][4];
#pragma unroll
    for (int i = 0; i < 8; i++)
#pragma unroll
        for (int jp = 0; jp < 4; jp++) acc2[i][jp] = 0ULL;

    // prologue: fill buffer 0 (k-slice [0,16))
    {
        float4 a0 = loadA4(ks);
        float4 a1 = loadA4(ks + 4);
        float4 q0 = *(const float4*)(Wb + (size_t)ar * K + ks);
        float4 q1 = *(const float4*)(Wb + (size_t)ar * K + ks + 4);
        As[0][ks+0][ar] = a0.x; As[0][ks+1][ar] = a0.y;
        As[0][ks+2][ar] = a0.z; As[0][ks+3][ar] = a0.w;
        As[0][ks+4][ar] = a1.x; As[0][ks+5][ar] = a1.y;
        As[0][ks+6][ar] = a1.z; As[0][ks+7][ar] = a1.w;
        Bs[0][ks+0][ar] = q0.x; Bs[0][ks+1][ar] = q0.y;
        Bs[0][ks+2][ar] = q0.z; Bs[0][ks+3][ar] = q0.w;
        Bs[0][ks+4][ar] = q1.x; Bs[0][ks+5][ar] = q1.y;
        Bs[0][ks+6][ar] = q1.z; Bs[0][ks+7][ar] = q1.w;
    }
    __syncthreads();

    const uint32_t bs_base = (uint32_t)__cvta_generic_to_shared(&Bs[0][0][0]);

    const int NK = K / 16;
#pragma unroll 1
    for (int kt = 0; kt < NK; kt++) {
        const int buf = kt & 1;
        float4 na0, na1, nq0, nq1;
        if (kt + 1 < NK) {
            const int kb = (kt + 1) * 16;
            na0 = loadA4(kb + ks);
            na1 = loadA4(kb + ks + 4);
            nq0 = *(const float4*)(Wb + (size_t)ar * K + kb + ks);
            nq1 = *(const float4*)(Wb + (size_t)ar * K + kb + ks + 4);
        }
        const uint32_t bbase = bs_base + ((uint32_t)buf * 2048 + (uint32_t)tx * 4) * 4;
#pragma unroll
        for (int k = 0; k < 16; k++) {
            float4 a0 = *(const float4*)&As[buf][k][ty * 8];
            float4 a1 = *(const float4*)&As[buf][k][ty * 8 + 4];
            unsigned long long b2[4];
            uint32_t baddr = bbase + (uint32_t)k * 512;
            asm volatile("ld.shared.v2.b64 {%0,%1}, [%2];"
                         : "=l"(b2[0]), "=l"(b2[1]) : "r"(baddr));
            asm volatile("ld.shared.v2.b64 {%0,%1}, [%2];"
                         : "=l"(b2[2]), "=l"(b2[3]) : "r"(baddr + 256));
            float ra[8] = {a0.x, a0.y, a0.z, a0.w, a1.x, a1.y, a1.z, a1.w};
#pragma unroll
            for (int i = 0; i < 8; i++) {
                unsigned long long ad;
                asm("mov.b64 %0, {%1, %1};" : "=l"(ad) : "f"(ra[i]));
                asm("fma.rn.f32x2 %0, %1, %2, %0;" : "+l"(acc2[i][0]) : "l"(ad), "l"(b2[0]));
                asm("fma.rn.f32x2 %0, %1, %2, %0;" : "+l"(acc2[i][1]) : "l"(ad), "l"(b2[1]));
                asm("fma.rn.f32x2 %0, %1, %2, %0;" : "+l"(acc2[i][2]) : "l"(ad), "l"(b2[2]));
                asm("fma.rn.f32x2 %0, %1, %2, %0;" : "+l"(acc2[i][3]) : "l"(ad), "l"(b2[3]));
            }
        }
        if (kt + 1 < NK) {
            const int nb = buf ^ 1;
            As[nb][ks+0][ar] = na0.x; As[nb][ks+1][ar] = na0.y;
            As[nb][ks+2][ar] = na0.z; As[nb][ks+3][ar] = na0.w;
            As[nb][ks+4][ar] = na1.x; As[nb][ks+5][ar] = na1.y;
            As[nb][ks+6][ar] = na1.z; As[nb][ks+7][ar] = na1.w;
            Bs[nb][ks+0][ar] = nq0.x; Bs[nb][ks+1][ar] = nq0.y;
            Bs[nb][ks+2][ar] = nq0.z; Bs[nb][ks+3][ar] = nq0.w;
            Bs[nb][ks+4][ar] = nq1.x; Bs[nb][ks+5][ar] = nq1.y;
            Bs[nb][ks+6][ar] = nq1.z; Bs[nb][ks+7][ar] = nq1.w;
        }
        __syncthreads();
    }

    // unpack accumulators (same column mapping as scalar version)
    float acc[8][8];
#pragma unroll
    for (int i = 0; i < 8; i++)
#pragma unroll
        for (int jp = 0; jp < 4; jp++) {
            asm("mov.b64 {%0, %1}, %2;"
                : "=f"(acc[i][2*jp+0]), "=f"(acc[i][2*jp+1]) : "l"(acc2[i][jp]));
        }

    // ---- C store ----
    float* Cb = Cdst + (size_t)(row0 + ty * 8) * COUT + blockIdx.x * 128;
#pragma unroll
    for (int i = 0; i < 8; i++) {
        *(float4*)(Cb + (size_t)i * COUT + tx * 4)      = make_float4(acc[i][0], acc[i][1], acc[i][2], acc[i][3]);
        *(float4*)(Cb + (size_t)i * COUT + 64 + tx * 4) = make_float4(acc[i][4], acc[i][5], acc[i][6], acc[i][7]);
    }

    // ---- BN-stat epilogue (deterministic fixed-order reduce) ----
    float cs[8], cq[8];
#pragma unroll
    for (int j = 0; j < 8; j++) { cs[j] = 0.f; cq[j] = 0.f; }
#pragma unroll
    for (int i = 0; i < 8; i++)
#pragma unroll
        for (int j = 0; j < 8; j++) {
            float v = acc[i][j];
            cs[j] += v;
            cq[j] = fmaf(v, v, cq[j]);
        }
    float (*ps)[128] = reinterpret_cast<float(*)[128]>(&As[0][0][0]);
    float (*pq)[128] = reinterpret_cast<float(*)[128]>(&Bs[0][0][0]);
    __syncthreads();
#pragma unroll
    for (int j = 0; j < 4; j++) {
        ps[ty][tx*4 + j]      = cs[j];
        pq[ty][tx*4 + j]      = cq[j];
        ps[ty][64 + tx*4 + j] = cs[4 + j];
        pq[ty][64 + tx*4 + j] = cq[4 + j];
    }
    __syncthreads();
    if (tid < 128) {
        float sv = 0.f, qv = 0.f;
#pragma unroll
        for (int t16 = 0; t16 < 16; t16++) { sv += ps[t16][tid]; qv += pq[t16][tid]; }
        int c = blockIdx.x * 128 + tid;
        g_psum[(size_t)c * PARTS + blockIdx.y] = sv;
        g_psq [(size_t)c * PARTS + blockIdx.y] = qv;
    }
}

// ---------------- 3) parallel BN finalize (one block per column) ------------
__global__ __launch_bounds__(256) void finalize_par(
    const float* __restrict__ gamma,
    const float* __restrict__ beta,
    int N, int nblk)
{
    __shared__ double sd[256], sq[256];
    const int c = blockIdx.x;
    const int t = threadIdx.x;
    double v = 0.0, q = 0.0;
    for (int b = t; b < nblk; b += 256) {
        v += (double)g_psum[(size_t)c * PARTS + b];
        q += (double)g_psq [(size_t)c * PARTS + b];
    }
    sd[t] = v; sq[t] = q;
    __syncthreads();
    for (int off = 128; off > 0; off >>= 1) {
        if (t < off) { sd[t] += sd[t + off]; sq[t] += sq[t + off]; }
        __syncthreads();
    }
    if (t == 0) {
        double mean = sd[0] / (double)N;
        double var  = sq[0] / (double)N - mean * mean;
        float  sc   = gamma[c] * rsqrtf((float)var + 1e-5f);
        g_scale[c] = sc;
        g_shift[c] = beta[c] - (float)mean * sc;
    }
}

// ---------------- 4) final BN apply + ReLU (vectorized) ----------------------
__global__ void bn_relu_out4(const float4* __restrict__ H, float4* __restrict__ out, int total4)
{
    int t = blockIdx.x * blockDim.x + threadIdx.x;
    if (t < total4) {
        int c = (t & 63) * 4;
        float4 v = H[t];
        v.x = fmaxf(fmaf(v.x, g_scale[c+0], g_shift[c+0]), 0.f);
        v.y = fmaxf(fmaf(v.y, g_scale[c+1], g_shift[c+1]), 0.f);
        v.z = fmaxf(fmaf(v.z, g_scale[c+2], g_shift[c+2]), 0.f);
        v.w = fmaxf(fmaf(v.w, g_scale[c+3], g_shift[c+3]), 0.f);
        out[t] = v;
    }
}

// ---------------- launch -----------------------------------------------------
extern "C" void kernel_launch(void* const* d_in, const int* in_sizes, int n_in,
                              void* d_out, int out_size)
{
    const float* unknown = (const float*)d_in[0];
    const int*   ub_cnt  = (const int*)  d_in[1];
    const float* known   = (const float*)d_in[2];
    const int*   kb_cnt  = (const int*)  d_in[3];
    const float* uf      = (const float*)d_in[4];
    const float* kf      = (const float*)d_in[5];
    const float* W1      = (const float*)d_in[6];
    const float* g1      = (const float*)d_in[7];
    const float* b1      = (const float*)d_in[8];
    const float* W2      = (const float*)d_in[9];
    const float* g2      = (const float*)d_in[10];
    const float* b2      = (const float*)d_in[11];
    float* out = (float*)d_out;

    int N = in_sizes[0] / 3;
    int B = in_sizes[1];
    int nblk = N / 128;
    int total4 = (int)(((long)N * COUT) / 4);

    float* Hp = nullptr; float* H2p = nullptr;
    cudaGetSymbolAddress((void**)&Hp,  g_H);
    cudaGetSymbolAddress((void**)&H2p, g_H2);

    // launch 0: nop — shifts ncu's "-s 5" capture window onto gemm2
    nop_kernel<<<1, 32>>>();

    three_nn_part<<<dim3((N + 511) / 512, NSPLIT), 256>>>(unknown, ub_cnt, known, kb_cnt, N, B);
    three_nn_merge<<<(N + 255) / 256, 256>>>(unknown, known, N);

    gemm_fused<384, 0><<<dim3(2, nblk), 256>>>(nullptr, kf, uf, W1, Hp);
    finalize_par<<<COUT, 256>>>(g1, b1, N, nblk);

    gemm_fused<256, 1><<<dim3(2, nblk), 256>>>(Hp, nullptr, nullptr, W2, H2p);
    finalize_par<<<COUT, 256>>>(g2, b2, N, nblk);

    bn_relu_out4<<<(total4 + 255) / 256, 256>>>((const float4*)H2p, (float4*)out, total4);
}

// round 16
// speedup vs baseline: 1.3617x; 1.2277x over previous
#include <cuda_runtime.h>
#include <cstdint>

// Problem-shape constants (fixed for this dataset)
#define NMAX  65536
#define MKF   16384            // known points
#define C1    128
#define C2    256
#define CIN   384
#define COUT  256
#define NN_TILE 512
#define NSPLIT 8               // per-batch known-axis splits for three_nn
#define PARTS 512              // max row-blocks (N/128)

// ---------------- scratch (device globals; no allocation allowed) ----------
__device__ float g_w[NMAX * 3];          // interpolation weights
__device__ int   g_i[NMAX * 3];          // 3-NN global indices
__device__ float g_ps[NSPLIT * NMAX * 3]; // partial top-3 scores per split
__device__ int   g_pi[NSPLIT * NMAX * 3]; // partial top-3 indices per split
__device__ float g_G [MKF  * COUT];      // G = kf @ W1a^T  (16 MB, L2-resident)
__device__ float g_H [NMAX * COUT];      // layer-1 pre-BN output
__device__ float g_H2[NMAX * COUT];      // layer-2 pre-BN output
__device__ float g_psum[COUT * PARTS];   // [col][rowblock] partial sums
__device__ float g_psq [COUT * PARTS];
__device__ float g_scale[COUT];
__device__ float g_shift[COUT];

// ---------------- 0) nop kernel (profiling alignment) ------------------------
__global__ void nop_kernel() {}

// ---------------- 1a) 3-NN partial pass (2 pts/thread, 8-way per-batch split)
__global__ __launch_bounds__(256) void three_nn_part(
    const float* __restrict__ unknown,
    const int*   __restrict__ ub_cnt,
    const float* __restrict__ known,
    const int*   __restrict__ kb_cnt,
    int N, int B)
{
    __shared__ float4 sk[NN_TILE];

    const int tid  = threadIdx.x;
    const int s    = blockIdx.y;
    const int base = blockIdx.x * 512;
    const int n0 = base + tid;
    const int n1 = base + 256 + tid;

    float ux0 = 0.f, uy0 = 0.f, uz0 = 0.f;
    float ux1 = 0.f, uy1 = 0.f, uz1 = 0.f;
    int b0i = -1, b1i = -1;
    if (n0 < N) { ux0 = unknown[n0*3]; uy0 = unknown[n0*3+1]; uz0 = unknown[n0*3+2]; }
    if (n1 < N) { ux1 = unknown[n1*3]; uy1 = unknown[n1*3+1]; uz1 = unknown[n1*3+2]; }
    {
        int acc = 0;
        for (int b = 0; b < B; b++) {
            int nx = acc + ub_cnt[b];
            if (n0 < N && n0 >= acc && n0 < nx) b0i = b;
            if (n1 < N && n1 >= acc && n1 < nx) b1i = b;
            acc = nx;
        }
    }

    const float NEG = -__int_as_float(0x7f800000);
    float s00 = NEG, s01 = NEG, s02 = NEG;
    float s10 = NEG, s11 = NEG, s12 = NEG;
    int   a00 = 0, a01 = 0, a02 = 0;
    int   a10 = 0, a11 = 0, a12 = 0;

    int kacc = 0;
    for (int b = 0; b < B; b++) {
        int ks = kacc;
        kacc += kb_cnt[b];
        int ke = kacc;
        bool act0 = (b0i == b), act1 = (b1i == b);

        int tloc = 0;
        for (int t = ks; t < ke; t += NN_TILE, tloc++) {
            if ((tloc & (NSPLIT - 1)) != s) continue;
            int any = __syncthreads_or((int)(act0 || act1));
            if (!any) continue;

            int cnt = min(NN_TILE, ke - t);
            __syncthreads();
            for (int i = tid; i < cnt; i += 256) {
                float kx = known[(t + i) * 3 + 0];
                float ky = known[(t + i) * 3 + 1];
                float kz = known[(t + i) * 3 + 2];
                float h  = 0.5f * (kx * kx + ky * ky + kz * kz);
                sk[i] = make_float4(kx, ky, kz, h);
            }
            __syncthreads();

#pragma unroll 4
            for (int j = 0; j < cnt; j++) {
                float4 kk = sk[j];
                int gi = t + j;
                float t0 = fmaf(ux0, kk.x, fmaf(uy0, kk.y, fmaf(uz0, kk.z, -kk.w)));
                float t1 = fmaf(ux1, kk.x, fmaf(uy1, kk.y, fmaf(uz1, kk.z, -kk.w)));
                t0 = act0 ? t0 : NEG;
                t1 = act1 ? t1 : NEG;
                if (t0 > s02) {
                    if (t0 > s01) {
                        s02 = s01; a02 = a01;
                        if (t0 > s00) { s01 = s00; a01 = a00; s00 = t0; a00 = gi; }
                        else          { s01 = t0;  a01 = gi; }
                    } else { s02 = t0; a02 = gi; }
                }
                if (t1 > s12) {
                    if (t1 > s11) {
                        s12 = s11; a12 = a11;
                        if (t1 > s10) { s11 = s10; a11 = a10; s10 = t1; a10 = gi; }
                        else          { s11 = t1;  a11 = gi; }
                    } else { s12 = t1; a12 = gi; }
                }
            }
        }
    }

    if (n0 < N) {
        size_t o = ((size_t)s * N + n0) * 3;
        g_ps[o+0] = s00; g_ps[o+1] = s01; g_ps[o+2] = s02;
        g_pi[o+0] = a00; g_pi[o+1] = a01; g_pi[o+2] = a02;
    }
    if (n1 < N) {
        size_t o = ((size_t)s * N + n1) * 3;
        g_ps[o+0] = s10; g_ps[o+1] = s11; g_ps[o+2] = s12;
        g_pi[o+0] = a10; g_pi[o+1] = a11; g_pi[o+2] = a12;
    }
}

// ---------------- 1b) merge partials -> weights + indices -------------------
__global__ void three_nn_merge(const float* __restrict__ unknown,
                               const float* __restrict__ known,
                               int N)
{
    int n = blockIdx.x * blockDim.x + threadIdx.x;
    if (n >= N) return;

    float cs[NSPLIT * 3];
    int   ci[NSPLIT * 3];
#pragma unroll
    for (int s = 0; s < NSPLIT; s++) {
        size_t o = ((size_t)s * N + n) * 3;
#pragma unroll
        for (int q = 0; q < 3; q++) {
            cs[s*3+q] = g_ps[o+q];
            ci[s*3+q] = g_pi[o+q];
        }
    }

    const float NEG = -__int_as_float(0x7f800000);
    int   wi[3];
#pragma unroll
    for (int pass = 0; pass < 3; pass++) {
        float bs = NEG; int bidx = 0x7fffffff; int bk = 0;
#pragma unroll
        for (int k = 0; k < NSPLIT * 3; k++) {
            bool better = (cs[k] > bs) || (cs[k] == bs && ci[k] < bidx);
            if (better) { bs = cs[k]; bidx = ci[k]; bk = k; }
        }
        wi[pass] = bidx;
        cs[bk] = NEG; ci[bk] = 0x7fffffff;
    }

    float ux = unknown[n*3], uy = unknown[n*3+1], uz = unknown[n*3+2];
    float d[3];
#pragma unroll
    for (int q = 0; q < 3; q++) {
        int ai = wi[q];
        float dx = ux - known[ai*3+0];
        float dy = uy - known[ai*3+1];
        float dz = uz - known[ai*3+2];
        d[q] = dx*dx + dy*dy + dz*dz;
    }
    float r0 = 1.f/(d[0]+1e-8f), r1 = 1.f/(d[1]+1e-8f), r2 = 1.f/(d[2]+1e-8f);
    float sm = 1.f/(r0+r1+r2);
    g_w[n*3+0] = r0*sm; g_w[n*3+1] = r1*sm; g_w[n*3+2] = r2*sm;
    g_i[n*3+0] = wi[0]; g_i[n*3+1] = wi[1]; g_i[n*3+2] = wi[2];
}

// ---------------- 2) fused SGEMM family (R10-proven mainloop) ----------------
// C[m,o] = sum_k A[m,k] * W[o,k]; 128x128 tile, 256 thr, 8x8 microtile,
// k-tile 16, double-buffered, packed fma.rn.f32x2 inner loop.
// W row stride = WS (supports using a column slice of W1).
// MODE 1: A = relu(bn(Asrc)) via g_scale/g_shift; BN-stat epilogue  (gemm2)
// MODE 2: A = Asrc plain; no stats                                  (G = kf@W1a^T)
// MODE 3: A = Asrc plain (uf); epilogue adds w-gather of Gsrc; stats (layer 1)
template <int K, int WS, int MODE>
__global__ __launch_bounds__(256, 2) void gemm_fused(
    const float* __restrict__ Asrc,
    const float* __restrict__ Gsrc,
    const float* __restrict__ W,
    float* __restrict__ Cdst)
{
    __shared__ float As[2][16][128];
    __shared__ float Bs[2][16][128];
    __shared__ float ssc[256], ssh[256];

    const int tid = threadIdx.x;
    const int tx = tid & 15;
    const int ty = tid >> 4;
    const int ar = tid >> 1;
    const int ks = (tid & 1) * 8;
    const int row0 = blockIdx.y * 128;
    const float* Wb = W + (size_t)blockIdx.x * 128 * WS;

    if (MODE == 1) { ssc[tid] = g_scale[tid]; ssh[tid] = g_shift[tid]; }

    const int n = row0 + ar;
    if (MODE == 1) __syncthreads();

    auto loadA4 = [&](int k0) -> float4 {
        float4 v;
        if (MODE == 1) {
            v = *(const float4*)(Asrc + (size_t)n * K + k0);
            v.x = fmaxf(fmaf(v.x, ssc[k0+0], ssh[k0+0]), 0.f);
            v.y = fmaxf(fmaf(v.y, ssc[k0+1], ssh[k0+1]), 0.f);
            v.z = fmaxf(fmaf(v.z, ssc[k0+2], ssh[k0+2]), 0.f);
            v.w = fmaxf(fmaf(v.w, ssc[k0+3], ssh[k0+3]), 0.f);
        } else {
            v = *(const float4*)(Asrc + (size_t)n * K + k0);
        }
        return v;
    };

    unsigned long long acc2[8][4];
#pragma unroll
    for (int i = 0; i < 8; i++)
#pragma unroll
        for (int jp = 0; jp < 4; jp++) acc2[i][jp] = 0ULL;

    {
        float4 a0 = loadA4(ks);
        float4 a1 = loadA4(ks + 4);
        float4 q0 = *(const float4*)(Wb + (size_t)ar * WS + ks);
        float4 q1 = *(const float4*)(Wb + (size_t)ar * WS + ks + 4);
        As[0][ks+0][ar] = a0.x; As[0][ks+1][ar] = a0.y;
        As[0][ks+2][ar] = a0.z; As[0][ks+3][ar] = a0.w;
        As[0][ks+4][ar] = a1.x; As[0][ks+5][ar] = a1.y;
        As[0][ks+6][ar] = a1.z; As[0][ks+7][ar] = a1.w;
        Bs[0][ks+0][ar] = q0.x; Bs[0][ks+1][ar] = q0.y;
        Bs[0][ks+2][ar] = q0.z; Bs[0][ks+3][ar] = q0.w;
        Bs[0][ks+4][ar] = q1.x; Bs[0][ks+5][ar] = q1.y;
        Bs[0][ks+6][ar] = q1.z; Bs[0][ks+7][ar] = q1.w;
    }
    __syncthreads();

    const uint32_t bs_base = (uint32_t)__cvta_generic_to_shared(&Bs[0][0][0]);

    const int NK = K / 16;
#pragma unroll 1
    for (int kt = 0; kt < NK; kt++) {
        const int buf = kt & 1;
        float4 na0, na1, nq0, nq1;
        if (kt + 1 < NK) {
            const int kb = (kt + 1) * 16;
            na0 = loadA4(kb + ks);
            na1 = loadA4(kb + ks + 4);
            nq0 = *(const float4*)(Wb + (size_t)ar * WS + kb + ks);
            nq1 = *(const float4*)(Wb + (size_t)ar * WS + kb + ks + 4);
        }
        const uint32_t bbase = bs_base + ((uint32_t)buf * 2048 + (uint32_t)tx * 4) * 4;
#pragma unroll
        for (int k = 0; k < 16; k++) {
            float4 a0 = *(const float4*)&As[buf][k][ty * 8];
            float4 a1 = *(const float4*)&As[buf][k][ty * 8 + 4];
            unsigned long long b2[4];
            uint32_t baddr = bbase + (uint32_t)k * 512;
            asm volatile("ld.shared.v2.b64 {%0,%1}, [%2];"
                         : "=l"(b2[0]), "=l"(b2[1]) : "r"(baddr));
            asm volatile("ld.shared.v2.b64 {%0,%1}, [%2];"
                         : "=l"(b2[2]), "=l"(b2[3]) : "r"(baddr + 256));
            float ra[8] = {a0.x, a0.y, a0.z, a0.w, a1.x, a1.y, a1.z, a1.w};
#pragma unroll
            for (int i = 0; i < 8; i++) {
                unsigned long long ad;
                asm("mov.b64 %0, {%1, %1};" : "=l"(ad) : "f"(ra[i]));
                asm("fma.rn.f32x2 %0, %1, %2, %0;" : "+l"(acc2[i][0]) : "l"(ad), "l"(b2[0]));
                asm("fma.rn.f32x2 %0, %1, %2, %0;" : "+l"(acc2[i][1]) : "l"(ad), "l"(b2[1]));
                asm("fma.rn.f32x2 %0, %1, %2, %0;" : "+l"(acc2[i][2]) : "l"(ad), "l"(b2[2]));
                asm("fma.rn.f32x2 %0, %1, %2, %0;" : "+l"(acc2[i][3]) : "l"(ad), "l"(b2[3]));
            }
        }
        if (kt + 1 < NK) {
            const int nb = buf ^ 1;
            As[nb][ks+0][ar] = na0.x; As[nb][ks+1][ar] = na0.y;
            As[nb][ks+2][ar] = na0.z; As[nb][ks+3][ar] = na0.w;
            As[nb][ks+4][ar] = na1.x; As[nb][ks+5][ar] = na1.y;
            As[nb][ks+6][ar] = na1.z; As[nb][ks+7][ar] = na1.w;
            Bs[nb][ks+0][ar] = nq0.x; Bs[nb][ks+1][ar] = nq0.y;
            Bs[nb][ks+2][ar] = nq0.z; Bs[nb][ks+3][ar] = nq0.w;
            Bs[nb][ks+4][ar] = nq1.x; Bs[nb][ks+5][ar] = nq1.y;
            Bs[nb][ks+6][ar] = nq1.z; Bs[nb][ks+7][ar] = nq1.w;
        }
        __syncthreads();
    }

    // unpack accumulators
    float acc[8][8];
#pragma unroll
    for (int i = 0; i < 8; i++)
#pragma unroll
        for (int jp = 0; jp < 4; jp++) {
            asm("mov.b64 {%0, %1}, %2;"
                : "=f"(acc[i][2*jp+0]), "=f"(acc[i][2*jp+1]) : "l"(acc2[i][jp]));
        }

    // ---- MODE 3: add weighted 3-row gather of G (layer-1 interp part) ----
    if (MODE == 3) {
        const int colbase = blockIdx.x * 128;
#pragma unroll 1
        for (int i = 0; i < 8; i++) {
            int nn = row0 + ty * 8 + i;
            float w0 = g_w[nn*3+0], w1 = g_w[nn*3+1], w2 = g_w[nn*3+2];
            int   j0 = g_i[nn*3+0], j1 = g_i[nn*3+1], j2 = g_i[nn*3+2];
            const float* G0 = Gsrc + (size_t)j0 * COUT + colbase;
            const float* G1 = Gsrc + (size_t)j1 * COUT + colbase;
            const float* G2 = Gsrc + (size_t)j2 * COUT + colbase;
            float4 p0 = *(const float4*)(G0 + tx*4);
            float4 p1 = *(const float4*)(G1 + tx*4);
            float4 p2 = *(const float4*)(G2 + tx*4);
            acc[i][0] += w0*p0.x + w1*p1.x + w2*p2.x;
            acc[i][1] += w0*p0.y + w1*p1.y + w2*p2.y;
            acc[i][2] += w0*p0.z + w1*p1.z + w2*p2.z;
            acc[i][3] += w0*p0.w + w1*p1.w + w2*p2.w;
            float4 r0v = *(const float4*)(G0 + 64 + tx*4);
            float4 r1v = *(const float4*)(G1 + 64 + tx*4);
            float4 r2v = *(const float4*)(G2 + 64 + tx*4);
            acc[i][4] += w0*r0v.x + w1*r1v.x + w2*r2v.x;
            acc[i][5] += w0*r0v.y + w1*r1v.y + w2*r2v.y;
            acc[i][6] += w0*r0v.z + w1*r1v.z + w2*r2v.z;
            acc[i][7] += w0*r0v.w + w1*r1v.w + w2*r2v.w;
        }
    }

    // ---- C store ----
    float* Cb = Cdst + (size_t)(row0 + ty * 8) * COUT + blockIdx.x * 128;
#pragma unroll
    for (int i = 0; i < 8; i++) {
        *(float4*)(Cb + (size_t)i * COUT + tx * 4)      = make_float4(acc[i][0], acc[i][1], acc[i][2], acc[i][3]);
        *(float4*)(Cb + (size_t)i * COUT + 64 + tx * 4) = make_float4(acc[i][4], acc[i][5], acc[i][6], acc[i][7]);
    }

    // ---- BN-stat epilogue (MODE 1 & 3) ----
    if (MODE == 1 || MODE == 3) {
        float cs[8], cq[8];
#pragma unroll
        for (int j = 0; j < 8; j++) { cs[j] = 0.f; cq[j] = 0.f; }
#pragma unroll
        for (int i = 0; i < 8; i++)
#pragma unroll
            for (int j = 0; j < 8; j++) {
                float v = acc[i][j];
                cs[j] += v;
                cq[j] = fmaf(v, v, cq[j]);
            }
        float (*ps)[128] = reinterpret_cast<float(*)[128]>(&As[0][0][0]);
        float (*pq)[128] = reinterpret_cast<float(*)[128]>(&Bs[0][0][0]);
        __syncthreads();
#pragma unroll
        for (int j = 0; j < 4; j++) {
            ps[ty][tx*4 + j]      = cs[j];
            pq[ty][tx*4 + j]      = cq[j];
            ps[ty][64 + tx*4 + j] = cs[4 + j];
            pq[ty][64 + tx*4 + j] = cq[4 + j];
        }
        __syncthreads();
        if (tid < 128) {
            float sv = 0.f, qv = 0.f;
#pragma unroll
            for (int t16 = 0; t16 < 16; t16++) { sv += ps[t16][tid]; qv += pq[t16][tid]; }
            int c = blockIdx.x * 128 + tid;
            g_psum[(size_t)c * PARTS + blockIdx.y] = sv;
            g_psq [(size_t)c * PARTS + blockIdx.y] = qv;
        }
    }
}

// ---------------- 3) parallel BN finalize (one block per column) ------------
__global__ __launch_bounds__(256) void finalize_par(
    const float* __restrict__ gamma,
    const float* __restrict__ beta,
    int N, int nblk)
{
    __shared__ double sd[256], sq[256];
    const int c = blockIdx.x;
    const int t = threadIdx.x;
    double v = 0.0, q = 0.0;
    for (int b = t; b < nblk; b += 256) {
        v += (double)g_psum[(size_t)c * PARTS + b];
        q += (double)g_psq [(size_t)c * PARTS + b];
    }
    sd[t] = v; sq[t] = q;
    __syncthreads();
    for (int off = 128; off > 0; off >>= 1) {
        if (t < off) { sd[t] += sd[t + off]; sq[t] += sq[t + off]; }
        __syncthreads();
    }
    if (t == 0) {
        double mean = sd[0] / (double)N;
        double var  = sq[0] / (double)N - mean * mean;
        float  sc   = gamma[c] * rsqrtf((float)var + 1e-5f);
        g_scale[c] = sc;
        g_shift[c] = beta[c] - (float)mean * sc;
    }
}

// ---------------- 4) final BN apply + ReLU (vectorized) ----------------------
__global__ void bn_relu_out4(const float4* __restrict__ H, float4* __restrict__ out, int total4)
{
    int t = blockIdx.x * blockDim.x + threadIdx.x;
    if (t < total4) {
        int c = (t & 63) * 4;
        float4 v = H[t];
        v.x = fmaxf(fmaf(v.x, g_scale[c+0], g_shift[c+0]), 0.f);
        v.y = fmaxf(fmaf(v.y, g_scale[c+1], g_shift[c+1]), 0.f);
        v.z = fmaxf(fmaf(v.z, g_scale[c+2], g_shift[c+2]), 0.f);
        v.w = fmaxf(fmaf(v.w, g_scale[c+3], g_shift[c+3]), 0.f);
        out[t] = v;
    }
}

// ---------------- launch -----------------------------------------------------
extern "C" void kernel_launch(void* const* d_in, const int* in_sizes, int n_in,
                              void* d_out, int out_size)
{
    const float* unknown = (const float*)d_in[0];
    const int*   ub_cnt  = (const int*)  d_in[1];
    const float* known   = (const float*)d_in[2];
    const int*   kb_cnt  = (const int*)  d_in[3];
    const float* uf      = (const float*)d_in[4];
    const float* kf      = (const float*)d_in[5];
    const float* W1      = (const float*)d_in[6];
    const float* g1      = (const float*)d_in[7];
    const float* b1      = (const float*)d_in[8];
    const float* W2      = (const float*)d_in[9];
    const float* g2      = (const float*)d_in[10];
    const float* b2      = (const float*)d_in[11];
    float* out = (float*)d_out;

    int N  = in_sizes[0] / 3;          // 65536 unknowns
    int Mk = in_sizes[2] / 3;          // 16384 knowns
    int B  = in_sizes[1];
    int nblk  = N  / 128;
    int nblkG = Mk / 128;
    int total4 = (int)(((long)N * COUT) / 4);

    float* Hp = nullptr; float* H2p = nullptr; float* Gp = nullptr;
    cudaGetSymbolAddress((void**)&Hp,  g_H);
    cudaGetSymbolAddress((void**)&H2p, g_H2);
    cudaGetSymbolAddress((void**)&Gp,  g_G);

    nop_kernel<<<1, 32>>>();

    three_nn_part<<<dim3((N + 511) / 512, NSPLIT), 256>>>(unknown, ub_cnt, known, kb_cnt, N, B);
    three_nn_merge<<<(N + 255) / 256, 256>>>(unknown, known, N);

    // G = kf @ W1a^T  (W1a = first 256 columns of W1, row stride 384)
    gemm_fused<256, CIN, 2><<<dim3(2, nblkG), 256>>>(kf, nullptr, W1, Gp);

    // H1 = uf @ W1b^T + weighted gather of G   (W1b = cols 256..383 of W1)
    gemm_fused<128, CIN, 3><<<dim3(2, nblk), 256>>>(uf, Gp, W1 + C2, Hp);
    finalize_par<<<COUT, 256>>>(g1, b1, N, nblk);

    // H2 = relu(bn(H1)) @ W2^T
    gemm_fused<256, COUT, 1><<<dim3(2, nblk), 256>>>(Hp, nullptr, W2, H2p);
    finalize_par<<<COUT, 256>>>(g2, b2, N, nblk);

    bn_relu_out4<<<(total4 + 255) / 256, 256>>>((const float4*)H2p, (float4*)out, total4);
}